// round 2
// baseline (speedup 1.0000x reference)
#include <cuda_runtime.h>

#define N_NODES 50000
#define N_EDGES 1600000
#define HEADS 8
#define OUT_FEAT 16
#define IN_FEAT 128
#define HF 128            // HEADS*OUT_FEAT

// ---- scratch (device globals: no allocations allowed) ----
__device__ float4   g_h4[N_NODES * 32];        // h as float4 [N][H][4x float4] = 25.6 MB
__device__ float4   g_post[N_NODES * HEADS];   // (loc_l, loc_r, lsl, lsr) per node-head, 6.4 MB
__device__ float    g_e[N_EDGES * HEADS];      // edge scores -> exp values, 51.2 MB
__device__ unsigned g_m[N_NODES * HEADS];      // encoded segment max, 1.6 MB
__device__ float    g_denom[N_NODES * HEADS];  // softmax denom -> reciprocal, 1.6 MB

// monotone float<->uint encoding so atomicMax(unsigned) == float max
__device__ __forceinline__ unsigned fenc(float f) {
    unsigned u = __float_as_uint(f);
    return (u & 0x80000000u) ? ~u : (u | 0x80000000u);
}
__device__ __forceinline__ float fdec(unsigned u) {
    return __uint_as_float((u & 0x80000000u) ? (u & 0x7FFFFFFFu) : ~u);
}

// ---- init: out = bias, m = -inf(encoded 0), denom = 0 ----
__global__ void k_init(const float* __restrict__ bias, float* __restrict__ out) {
    int i = blockIdx.x * blockDim.x + threadIdx.x;
    if (i < N_NODES * HF) out[i] = bias[i & (HF - 1)];
    if (i < N_NODES * HEADS) { g_m[i] = 0u; g_denom[i] = 0.0f; }
}

// ---- projection: h = feat @ W_fc ; post = h @ W_post + b_post ----
// block: 256 threads, 32 nodes per block. thread t -> node t/8, head t%8 (16 cols).
__global__ void k_proj(const float* __restrict__ feat, const float* __restrict__ W_fc,
                       const float* __restrict__ W_post, const float* __restrict__ b_post) {
    __shared__ float sf[32][IN_FEAT];   // 16 KB
    __shared__ float sw[32][HF];        // 16 KB
    int t = threadIdx.x;
    int n0 = blockIdx.x * 32;

    // load feat tile (zero-pad tail)
    for (int i = t; i < 32 * IN_FEAT; i += 256) {
        int r = i >> 7, c = i & 127;
        int n = n0 + r;
        sf[r][c] = (n < N_NODES) ? feat[n * IN_FEAT + c] : 0.0f;
    }

    float acc[16];
#pragma unroll
    for (int j = 0; j < 16; ++j) acc[j] = 0.0f;

    int r  = t >> 3;        // node within tile
    int hd = t & 7;         // head
    int c0 = hd * 16;

    for (int kc = 0; kc < IN_FEAT; kc += 32) {
        __syncthreads();
        for (int i = t; i < 32 * HF; i += 256) {
            int kk = i >> 7, c = i & 127;
            sw[kk][c] = W_fc[(kc + kk) * HF + c];
        }
        __syncthreads();
#pragma unroll 8
        for (int kk = 0; kk < 32; ++kk) {
            float a = sf[r][kc + kk];
#pragma unroll
            for (int j = 0; j < 16; ++j) acc[j] = fmaf(a, sw[kk][c0 + j], acc[j]);
        }
    }

    int n = n0 + r;
    if (n < N_NODES) {
        // write h as float4s
#pragma unroll
        for (int q = 0; q < 4; ++q)
            g_h4[n * 32 + hd * 4 + q] =
                make_float4(acc[4 * q], acc[4 * q + 1], acc[4 * q + 2], acc[4 * q + 3]);
        // post params for (n, hd)
        float p0 = b_post[0], p1 = b_post[1], p2 = b_post[2], p3 = b_post[3];
#pragma unroll
        for (int j = 0; j < 16; ++j) {
            float hv = acc[j];
            p0 = fmaf(hv, W_post[j * 4 + 0], p0);
            p1 = fmaf(hv, W_post[j * 4 + 1], p1);
            p2 = fmaf(hv, W_post[j * 4 + 2], p2);
            p3 = fmaf(hv, W_post[j * 4 + 3], p3);
        }
        g_post[n * HEADS + hd] = make_float4(p0, p1, p2, p3);
    }
}

// ---- per-edge score + segment max ----
__global__ void k_edge(const int* __restrict__ src, const int* __restrict__ dst,
                       const float* __restrict__ eps) {
    int i = blockIdx.x * blockDim.x + threadIdx.x;
    if (i >= N_EDGES * HEADS) return;
    int e = i >> 3, hd = i & 7;
    int s = src[e], d = dst[e];
    float4 ps = g_post[s * HEADS + hd];
    float4 pd = g_post[d * HEADS + hd];
    float ev = (ps.x + pd.y) + __expf(ps.z + pd.w) * eps[i];
    g_e[i] = ev;
    atomicMax(&g_m[d * HEADS + hd], fenc(ev));
}

// ---- exp(e - m) + denom accumulate ----
__global__ void k_soft(const int* __restrict__ dst) {
    int i = blockIdx.x * blockDim.x + threadIdx.x;
    if (i >= N_EDGES * HEADS) return;
    int e = i >> 3, hd = i & 7;
    int d = dst[e];
    float m  = fdec(g_m[d * HEADS + hd]);
    float ex = __expf(g_e[i] - m);
    g_e[i] = ex;
    atomicAdd(&g_denom[d * HEADS + hd], ex);
}

// ---- reciprocal of denom (avoid 12.8M divides in aggregation) ----
__global__ void k_recip() {
    int i = blockIdx.x * blockDim.x + threadIdx.x;
    if (i < N_NODES * HEADS) g_denom[i] = 1.0f / g_denom[i];
}

// ---- aggregation: one warp per edge ----
// lane l: head = l>>2, float4 chunk = l&3. 32 lanes cover the 128 output floats.
__global__ void k_agg(const int* __restrict__ src, const int* __restrict__ dst,
                      float* __restrict__ out) {
    int gw   = (int)((blockIdx.x * (unsigned)blockDim.x + threadIdx.x) >> 5);
    int lane = threadIdx.x & 31;
    if (gw >= N_EDGES) return;
    int s = src[gw], d = dst[gw];
    int hd = lane >> 2;
    float a = g_e[gw * HEADS + hd] * g_denom[d * HEADS + hd];
    float4 hv = g_h4[s * 32 + hd * 4 + (lane & 3)];
    float4 v = make_float4(hv.x * a, hv.y * a, hv.z * a, hv.w * a);
    float* op = out + d * HF + (lane << 2);
    asm volatile("red.global.add.v4.f32 [%0], {%1,%2,%3,%4};"
                 :: "l"(op), "f"(v.x), "f"(v.y), "f"(v.z), "f"(v.w) : "memory");
}

extern "C" void kernel_launch(void* const* d_in, const int* in_sizes, int n_in,
                              void* d_out, int out_size) {
    const float* feat   = (const float*)d_in[0];
    const int*   src    = (const int*)  d_in[1];
    const int*   dst    = (const int*)  d_in[2];
    const float* eps    = (const float*)d_in[3];
    const float* W_fc   = (const float*)d_in[4];
    const float* W_post = (const float*)d_in[5];
    const float* b_post = (const float*)d_in[6];
    const float* bias   = (const float*)d_in[7];
    float* out = (float*)d_out;

    k_init <<<(N_NODES * HF + 255) / 256, 256>>>(bias, out);
    k_proj <<<(N_NODES + 31) / 32, 256>>>(feat, W_fc, W_post, b_post);
    k_edge <<<(N_EDGES * HEADS + 255) / 256, 256>>>(src, dst, eps);
    k_soft <<<(N_EDGES * HEADS + 255) / 256, 256>>>(dst);
    k_recip<<<(N_NODES * HEADS + 255) / 256, 256>>>();
    // one warp per edge -> N_EDGES * 32 threads (Round-1 bug: was N_EDGES * 8)
    k_agg  <<<(int)(((long long)N_EDGES * 32 + 255) / 256), 256>>>(src, dst, out);
}